// round 2
// baseline (speedup 1.0000x reference)
#include <cuda_runtime.h>
#include <cuda_bf16.h>

#define MCTA 16
#define T_STEPS 128
#define KSTEPS 17
#define ACT_STRIDE 280   // bf16 elems per row (560B): conflict-free ldmatrix

// Packed weights: [tile][kstep][lane] as uint2 (4 bf16 = one B-fragment lane slice)
// GEMM1 (Wm0): tiles 0..31 ; GEMM2 (Wf10|Wf20|Wh0): 32..127 ; GEMM3 (Wm1): 128..159
__device__ uint2 g_Wpk[160 * 17 * 32];
__device__ float4 g_smallW4[768];

#define G1_OFF 0
#define G2_OFF (32 * 17 * 32)
#define G3_OFF (128 * 17 * 32)

// ---------------------------------------------------------------------------
// Prepack: transpose + bf16-quantize + zero-pad weights into fragment order.
// B-frag mapping for mma.m16n8k16 (row.col): lane t covers n = t/4,
// k = (t%4)*2 + {0,1} (+8 for reg1).  value = W[k][n] (W stored [fin][256]).
// ---------------------------------------------------------------------------
__global__ void prepack_kernel(
    const float* __restrict__ Wm0, const float* __restrict__ Wf10,
    const float* __restrict__ Wf20, const float* __restrict__ Wh0,
    const float* __restrict__ Wm1, const float* __restrict__ Wf11,
    const float* __restrict__ Wf21, const float* __restrict__ Wh1)
{
    const int total_u32 = 160 * 17 * 32 * 2;
    int idx = blockIdx.x * blockDim.x + threadIdx.x;
    if (idx < total_u32) {
        int r    = idx & 1;
        int lane = (idx >> 1) & 31;
        int tk   = idx >> 6;          // tile*17 + ks
        int ks   = tk % 17;
        int tile = tk / 17;
        int kk = ks * 16 + (lane & 3) * 2 + r * 8;
        const float* W; int fin; int ncol;
        if (tile < 32) {
            W = Wm0; fin = 260; ncol = tile * 8 + (lane >> 2);
        } else if (tile < 128) {
            int n2 = (tile - 32) * 8 + (lane >> 2);
            if (n2 < 256)      { W = Wf10; fin = 260; ncol = n2; }
            else if (n2 < 512) { W = Wf20; fin = 260; ncol = n2 - 256; }
            else               { W = Wh0;  fin = 262; ncol = n2 - 512; }
        } else {
            W = Wm1; fin = 262; ncol = (tile - 128) * 8 + (lane >> 2);
        }
        float v0 = (kk     < fin) ? W[(size_t)kk       * 256 + ncol] : 0.f;
        float v1 = (kk + 1 < fin) ? W[(size_t)(kk + 1) * 256 + ncol] : 0.f;
        __nv_bfloat162 p;
        p.x = __float2bfloat16(v0);
        p.y = __float2bfloat16(v1);
        reinterpret_cast<unsigned*>(g_Wpk)[idx] = *reinterpret_cast<unsigned*>(&p);
    } else if (idx < total_u32 + 768) {
        int j = idx - total_u32;
        float4 v = make_float4(0.f, 0.f, 0.f, 0.f);
        if (j < 256)      { v.x = Wf11[j * 2];        v.y = Wf11[j * 2 + 1]; }
        else if (j < 512) { int q = j - 256;
                            v.x = Wf21[q * 4]; v.y = Wf21[q * 4 + 1];
                            v.z = Wf21[q * 4 + 2]; v.w = Wf21[q * 4 + 3]; }
        else              { int q = j - 512;
                            v.x = Wh1[q * 2];  v.y = Wh1[q * 2 + 1]; }
        g_smallW4[j] = v;
    }
}

// ---------------------------------------------------------------------------
// Device helpers
// ---------------------------------------------------------------------------
__device__ __forceinline__ void mma16816(float* d, const unsigned* a, uint2 b) {
    asm volatile(
        "mma.sync.aligned.m16n8k16.row.col.f32.bf16.bf16.f32 "
        "{%0,%1,%2,%3}, {%4,%5,%6,%7}, {%8,%9}, {%0,%1,%2,%3};\n"
        : "+f"(d[0]), "+f"(d[1]), "+f"(d[2]), "+f"(d[3])
        : "r"(a[0]), "r"(a[1]), "r"(a[2]), "r"(a[3]), "r"(b.x), "r"(b.y));
}
__device__ __forceinline__ void ldmA(unsigned* a, unsigned addr) {
    asm volatile(
        "ldmatrix.sync.aligned.m8n8.x4.shared.b16 {%0,%1,%2,%3}, [%4];\n"
        : "=r"(a[0]), "=r"(a[1]), "=r"(a[2]), "=r"(a[3]) : "r"(addr));
}
__device__ __forceinline__ float tanha(float x) {
    float y; asm("tanh.approx.f32 %0, %1;" : "=f"(y) : "f"(x)); return y;
}

// K-pipelined GEMM: A from SMEM via ldmatrix (same frags all warps),
// B fragments streamed from L2 with 1-kstep prefetch.
template <int NT>
__device__ __forceinline__ void run_gemm(const uint2* __restrict__ wp,
                                         unsigned abase, float (&D)[NT][4]) {
    unsigned a[4], an[4];
    uint2 b[NT], bn[NT];
    ldmA(a, abase);
#pragma unroll
    for (int i = 0; i < NT; i++) b[i] = wp[i * KSTEPS * 32];
#pragma unroll 1
    for (int ks = 0; ks < KSTEPS; ks++) {
        int ksn = (ks + 1 < KSTEPS) ? ks + 1 : ks;
        ldmA(an, abase + (unsigned)ksn * 32u);
#pragma unroll
        for (int i = 0; i < NT; i++) bn[i] = wp[(i * KSTEPS + ksn) * 32];
#pragma unroll
        for (int i = 0; i < NT; i++) mma16816(D[i], a, b[i]);
#pragma unroll
        for (int i = 0; i < NT; i++) b[i] = bn[i];
        a[0] = an[0]; a[1] = an[1]; a[2] = an[2]; a[3] = an[3];
    }
}

// ---------------------------------------------------------------------------
// Main persistent kernel: 128 CTAs x 256 threads, 16 batch rows per CTA.
// ---------------------------------------------------------------------------
__global__ void __launch_bounds__(256, 1) egbrnn_main(
    const float* __restrict__ x, const float* __restrict__ target,
    const float* __restrict__ c0,
    const float* __restrict__ bm0, const float* __restrict__ bm1,
    const float* __restrict__ bf10, const float* __restrict__ bf11,
    const float* __restrict__ bf20, const float* __restrict__ bf21,
    const float* __restrict__ bh0, const float* __restrict__ bh1,
    float* __restrict__ out)
{
    __shared__ __align__(16) __nv_bfloat16 act[MCTA][ACT_STRIDE];
    __shared__ float sS[MCTA][4];
    __shared__ float Pm[MCTA][16];
    __shared__ float measS[MCTA][2];
    __shared__ float part[8][MCTA][8];
    __shared__ float bm0s[256], bm1s[256], bias2s[768], biasSs[8];
    __shared__ __align__(16) float smallWs[768][4];

    const int tid = threadIdx.x;
    const int w = tid >> 5, lane = tid & 31;
    const int b0 = blockIdx.x * MCTA;
    const int row0 = lane >> 2;
    const int cbase = (lane & 3) * 2;

    // ---- one-time shared init ----
    bm0s[tid] = bm0[tid];
    bm1s[tid] = bm1[tid];
    for (int i = tid; i < 768; i += 256)
        bias2s[i] = (i < 256) ? bf10[i] : (i < 512 ? bf20[i - 256] : bh0[i - 512]);
    if (tid < 8)
        biasSs[tid] = (tid < 2) ? bf11[tid] : (tid < 6 ? bf21[tid - 2] : bh1[tid - 6]);
    for (int i = tid; i < 768; i += 256)
        *reinterpret_cast<float4*>(smallWs[i]) = g_smallW4[i];
    // zero activation tail (cols 256..ACT_STRIDE): zero-padded weights make
    // these multiply to 0, but they must be FINITE.
    for (int i = tid; i < MCTA * (ACT_STRIDE - 256); i += 256) {
        int r = i / (ACT_STRIDE - 256), c = 256 + i % (ACT_STRIDE - 256);
        act[r][c] = __float2bfloat16(0.f);
    }
    // c = c0
    for (int i = tid; i < MCTA * 256; i += 256) {
        int r = i >> 8, j = i & 255;
        act[r][j] = __float2bfloat16(c0[(size_t)(b0 + r) * 256 + j]);
    }
    if (tid < MCTA) {
        int r = tid;
        float4 tg = *reinterpret_cast<const float4*>(
            &target[((size_t)(b0 + r) * T_STEPS) * 4]);
        sS[r][0] = tg.x; sS[r][1] = tg.y; sS[r][2] = tg.z; sS[r][3] = tg.w;
#pragma unroll
        for (int i = 0; i < 16; i++) Pm[r][i] = (i % 5 == 0) ? 1.f : 0.f;
        __nv_bfloat162 a01, a23;
        a01.x = __float2bfloat16(tg.x * (1.f / 60.f));
        a01.y = __float2bfloat16(tg.y * (1.f / 60.f));
        a23.x = __float2bfloat16(tg.z * (1.f / 60.f));
        a23.y = __float2bfloat16(tg.w * (1.f / 60.f));
        *reinterpret_cast<__nv_bfloat162*>(&act[r][256]) = a01;
        *reinterpret_cast<__nv_bfloat162*>(&act[r][258]) = a23;
    }
    __syncthreads();

    const unsigned abase =
        (unsigned)__cvta_generic_to_shared(&act[lane & 15][(lane >> 4) * 8]);
    const uint2* w1p = g_Wpk + G1_OFF + (w * 4) * KSTEPS * 32 + lane;
    const uint2* w2p = g_Wpk + G2_OFF + (w * 12) * KSTEPS * 32 + lane;
    const uint2* w3p = g_Wpk + G3_OFF + (w * 4) * KSTEPS * 32 + lane;

    for (int t = 0; t < T_STEPS; t++) {
        // ---- P1: GEMM1 (cu preactivation), input act = [c, sn, ...] ----
        float D1[4][4];
#pragma unroll
        for (int i = 0; i < 4; i++) { D1[i][0]=D1[i][1]=D1[i][2]=D1[i][3]=0.f; }
        run_gemm<4>(w1p, abase, D1);
        __syncthreads();  // all act reads of GEMM1 done

        // ---- P2: write cu (bf16) over c; load meas; write m2 tail ----
#pragma unroll
        for (int tt = 0; tt < 4; tt++) {
            int col = (w * 4 + tt) * 8 + cbase;
            float bv0 = bm0s[col], bv1 = bm0s[col + 1];
            __nv_bfloat162 h0, h1;
            h0.x = __float2bfloat16(tanha(D1[tt][0] + bv0));
            h0.y = __float2bfloat16(tanha(D1[tt][1] + bv1));
            h1.x = __float2bfloat16(tanha(D1[tt][2] + bv0));
            h1.y = __float2bfloat16(tanha(D1[tt][3] + bv1));
            *reinterpret_cast<__nv_bfloat162*>(&act[row0][col]) = h0;
            *reinterpret_cast<__nv_bfloat162*>(&act[row0 + 8][col]) = h1;
        }
        if (tid < MCTA) {
            int r = tid;
            float m0 = x[(((size_t)(b0 + r)) * T_STEPS + t) * 2 + 0];
            float m1 = x[(((size_t)(b0 + r)) * T_STEPS + t) * 2 + 1];
            measS[r][0] = m0; measS[r][1] = m1;
            __nv_bfloat162 mm;
            mm.x = __float2bfloat16(m0 * (1.f / 60.f));
            mm.y = __float2bfloat16(m1 * (1.f / 60.f));
            *reinterpret_cast<__nv_bfloat162*>(&act[r][260]) = mm;
        }
        __syncthreads();

        // ---- P3: fused GEMM2 (h1|h2|h3) + small layers (d, pv, hv) ----
        float D2[12][4];
#pragma unroll
        for (int i = 0; i < 12; i++) { D2[i][0]=D2[i][1]=D2[i][2]=D2[i][3]=0.f; }
        run_gemm<12>(w2p, abase, D2);
        float o8[16];
#pragma unroll
        for (int k = 0; k < 16; k++) o8[k] = 0.f;
#pragma unroll
        for (int tt = 0; tt < 12; tt++) {
            int tile = w * 12 + tt;
            int col = tile * 8 + cbase;
            int seg = tile >> 5;  // 0: Wf11 (d), 1: Wf21 (pv), 2: Wh1 (hv)
            float bb0 = bias2s[col], bb1 = bias2s[col + 1];
            float h00 = tanha(D2[tt][0] + bb0), h01 = tanha(D2[tt][1] + bb1);
            float h10 = tanha(D2[tt][2] + bb0), h11 = tanha(D2[tt][3] + bb1);
            float4 w0 = *reinterpret_cast<float4*>(smallWs[col]);
            float4 w1 = *reinterpret_cast<float4*>(smallWs[col + 1]);
            int ob = (seg == 0) ? 0 : ((seg == 1) ? 2 : 6);
            o8[ob + 0]     += h00 * w0.x + h01 * w1.x;
            o8[ob + 1]     += h00 * w0.y + h01 * w1.y;
            o8[8 + ob + 0] += h10 * w0.x + h11 * w1.x;
            o8[8 + ob + 1] += h10 * w0.y + h11 * w1.y;
            if (seg == 1) {
                o8[4]  += h00 * w0.z + h01 * w1.z;
                o8[5]  += h00 * w0.w + h01 * w1.w;
                o8[12] += h10 * w0.z + h11 * w1.z;
                o8[13] += h10 * w0.w + h11 * w1.w;
            }
        }
#pragma unroll
        for (int k = 0; k < 16; k++) {
            o8[k] += __shfl_xor_sync(0xffffffffu, o8[k], 1);
            o8[k] += __shfl_xor_sync(0xffffffffu, o8[k], 2);
        }
        if ((lane & 3) == 0) {
#pragma unroll
            for (int o = 0; o < 8; o++) {
                part[w][row0][o]     = o8[o];
                part[w][row0 + 8][o] = o8[8 + o];
            }
        }
        __syncthreads();

        // ---- P4: per-row Kalman update (fp32), tid<16 ----
        if (tid < MCTA) {
            const int r = tid;
            float sm[8];
#pragma unroll
            for (int o = 0; o < 8; o++) {
                float a = biasSs[o];
#pragma unroll
                for (int ww = 0; ww < 8; ww++) a += part[ww][r][o];
                sm[o] = a;
            }
            const float d0 = sm[0], d1 = sm[1];
            const float pv[4] = {sm[2], sm[3], sm[4], sm[5]};
            const float hv0 = sm[6], hv1 = sm[7];
            float s0 = sS[r][0], s1 = sS[r][1], s2 = sS[r][2], s3 = sS[r][3];
            float sp[4];
            sp[0] = s0 + s2 + 0.5f * d0;
            sp[1] = s1 + s3 + 0.5f * d1;
            sp[2] = s2 + d0;
            sp[3] = s3 + d1;
            float P[4][4];
#pragma unroll
            for (int i = 0; i < 4; i++)
#pragma unroll
                for (int j = 0; j < 4; j++) P[i][j] = Pm[r][i * 4 + j];
            float FP[4][4], Pp[4][4];
#pragma unroll
            for (int j = 0; j < 4; j++) {
                FP[0][j] = P[0][j] + P[2][j];
                FP[1][j] = P[1][j] + P[3][j];
                FP[2][j] = P[2][j];
                FP[3][j] = P[3][j];
            }
#pragma unroll
            for (int i = 0; i < 4; i++) {
                Pp[i][0] = FP[i][0] + FP[i][2];
                Pp[i][1] = FP[i][1] + FP[i][3];
                Pp[i][2] = FP[i][2];
                Pp[i][3] = FP[i][3];
            }
#pragma unroll
            for (int i = 0; i < 4; i++)
#pragma unroll
                for (int j = 0; j < 4; j++) Pp[i][j] += pv[i] * pv[j];
#pragma unroll
            for (int i = 0; i < 4; i++) Pp[i][i] += 0.01f;
            float m0 = measS[r][0], m1 = measS[r][1];
            float in0 = m0 - sp[0], in1 = m1 - sp[1];
            float S00 = Pp[0][0] + hv0 * hv0 + 1.f;
            float S01 = Pp[0][1] + hv0 * hv1;
            float S10 = Pp[1][0] + hv1 * hv0;
            float S11 = Pp[1][1] + hv1 * hv1 + 1.f;
            float inv = 1.0f / (S00 * S11 - S01 * S10);
            float K[4][2], KS[4][2], su[4];
#pragma unroll
            for (int i = 0; i < 4; i++) {
                K[i][0] = (Pp[i][0] * S11 - Pp[i][1] * S10) * inv;
                K[i][1] = (Pp[i][1] * S00 - Pp[i][0] * S01) * inv;
                su[i] = sp[i] + K[i][0] * in0 + K[i][1] * in1;
                KS[i][0] = K[i][0] * S00 + K[i][1] * S10;
                KS[i][1] = K[i][0] * S01 + K[i][1] * S11;
            }
#pragma unroll
            for (int i = 0; i < 4; i++)
#pragma unroll
                for (int j = 0; j < 4; j++)
                    Pm[r][i * 4 + j] =
                        Pp[i][j] - KS[i][0] * K[j][0] - KS[i][1] * K[j][1];
            sS[r][0] = su[0]; sS[r][1] = su[1];
            sS[r][2] = su[2]; sS[r][3] = su[3];
            float4 ov = make_float4(su[0], su[1], su[2], su[3]);
            *reinterpret_cast<float4*>(
                &out[(((size_t)(b0 + r)) * T_STEPS + t) * 4]) = ov;
            // GEMM3 tail: [m2(256:258), su/60(258:262)]
            __nv_bfloat162 mm, q0, q1;
            mm.x = __float2bfloat16(m0 * (1.f / 60.f));
            mm.y = __float2bfloat16(m1 * (1.f / 60.f));
            q0.x = __float2bfloat16(su[0] * (1.f / 60.f));
            q0.y = __float2bfloat16(su[1] * (1.f / 60.f));
            q1.x = __float2bfloat16(su[2] * (1.f / 60.f));
            q1.y = __float2bfloat16(su[3] * (1.f / 60.f));
            *reinterpret_cast<__nv_bfloat162*>(&act[r][256]) = mm;
            *reinterpret_cast<__nv_bfloat162*>(&act[r][258]) = q0;
            *reinterpret_cast<__nv_bfloat162*>(&act[r][260]) = q1;
        }
        __syncthreads();

        // ---- P5: GEMM3 (c_new preactivation), input [cu, m2, su] ----
        float D3[4][4];
#pragma unroll
        for (int i = 0; i < 4; i++) { D3[i][0]=D3[i][1]=D3[i][2]=D3[i][3]=0.f; }
        run_gemm<4>(w3p, abase, D3);
        __syncthreads();  // all act reads of GEMM3 done

        // ---- P6: write c_new over cu; refresh sn tail for next step ----
#pragma unroll
        for (int tt = 0; tt < 4; tt++) {
            int col = (w * 4 + tt) * 8 + cbase;
            float bv0 = bm1s[col], bv1 = bm1s[col + 1];
            __nv_bfloat162 h0, h1;
            h0.x = __float2bfloat16(tanha(D3[tt][0] + bv0));
            h0.y = __float2bfloat16(tanha(D3[tt][1] + bv1));
            h1.x = __float2bfloat16(tanha(D3[tt][2] + bv0));
            h1.y = __float2bfloat16(tanha(D3[tt][3] + bv1));
            *reinterpret_cast<__nv_bfloat162*>(&act[row0][col]) = h0;
            *reinterpret_cast<__nv_bfloat162*>(&act[row0 + 8][col]) = h1;
        }
        if (tid < MCTA) {
            int r = tid;
            __nv_bfloat162 a01, a23;
            a01.x = __float2bfloat16(sS[r][0] * (1.f / 60.f));
            a01.y = __float2bfloat16(sS[r][1] * (1.f / 60.f));
            a23.x = __float2bfloat16(sS[r][2] * (1.f / 60.f));
            a23.y = __float2bfloat16(sS[r][3] * (1.f / 60.f));
            *reinterpret_cast<__nv_bfloat162*>(&act[r][256]) = a01;
            *reinterpret_cast<__nv_bfloat162*>(&act[r][258]) = a23;
        }
        __syncthreads();
    }
}

// ---------------------------------------------------------------------------
extern "C" void kernel_launch(void* const* d_in, const int* in_sizes, int n_in,
                              void* d_out, int out_size)
{
    const float* x    = (const float*)d_in[0];
    const float* targ = (const float*)d_in[1];
    const float* c0   = (const float*)d_in[2];
    const float* Wm0  = (const float*)d_in[3];
    const float* bm0  = (const float*)d_in[4];
    const float* Wm1  = (const float*)d_in[5];
    const float* bm1  = (const float*)d_in[6];
    const float* Wf10 = (const float*)d_in[7];
    const float* bf10 = (const float*)d_in[8];
    const float* Wf11 = (const float*)d_in[9];
    const float* bf11 = (const float*)d_in[10];
    const float* Wf20 = (const float*)d_in[11];
    const float* bf20 = (const float*)d_in[12];
    const float* Wf21 = (const float*)d_in[13];
    const float* bf21 = (const float*)d_in[14];
    const float* Wh0  = (const float*)d_in[15];
    const float* bh0  = (const float*)d_in[16];
    const float* Wh1  = (const float*)d_in[17];
    const float* bh1  = (const float*)d_in[18];
    float* out = (float*)d_out;

    const int tot = 160 * 17 * 32 * 2 + 768;
    prepack_kernel<<<(tot + 255) / 256, 256>>>(Wm0, Wf10, Wf20, Wh0, Wm1,
                                               Wf11, Wf21, Wh1);
    egbrnn_main<<<128, 256>>>(x, targ, c0, bm0, bm1, bf10, bf11, bf20, bf21,
                              bh0, bh1, out);
}